// round 2
// baseline (speedup 1.0000x reference)
#include <cuda_runtime.h>
#include <cuda_bf16.h>
#include <math.h>

#define N_NODES 50000
#define N_EDGES 400000
#define D_EMB   512
#define HEADS   8
#define DK      32
#define DV      32
#define HD      (HEADS * DK)   // 256

// ---------------- scratch (device globals; no allocations allowed) ----------
__device__ float g_K[N_NODES * HD];
__device__ float g_Q[N_NODES * HD];
__device__ float g_V[N_NODES * HD];
__device__ float g_att[N_EDGES * HEADS];
__device__ float g_denom[N_NODES * HEADS];
__device__ float g_agg[N_NODES * HD];
__device__ float g_h1[N_NODES * D_EMB];

// ---------------- zero kernel (denom + agg) ---------------------------------
__global__ void zero_scratch() {
    const int n_denom = N_NODES * HEADS;
    const int n_agg   = N_NODES * HD;
    int total = n_denom + n_agg;
    for (int i = blockIdx.x * blockDim.x + threadIdx.x; i < total;
         i += gridDim.x * blockDim.x) {
        if (i < n_denom) g_denom[i] = 0.0f;
        else             g_agg[i - n_denom] = 0.0f;
    }
}

// ---------------- SGEMM: C = op(A) @ B + bias, optional relu/residual -------
// A: [M,K] row-major, B: [K,N] row-major, bias: [N]
template<bool RELU_A, bool RELU_OUT, bool RES>
__global__ __launch_bounds__(256)
void sgemm128(const float* __restrict__ A, const float* __restrict__ B,
              const float* __restrict__ bias, const float* __restrict__ res,
              float* __restrict__ C, int M, int N, int K)
{
    __shared__ float As[8][128];
    __shared__ float Bs[8][128];

    const int tid  = threadIdx.x;
    const int row0 = blockIdx.y * 128;
    const int col0 = blockIdx.x * 128;

    const int arow = tid >> 1;
    const int acol = (tid & 1) * 4;
    const int brow = tid >> 5;
    const int bcol = (tid & 31) * 4;

    const int tm = (tid >> 4) * 8;
    const int tn = (tid & 15) * 8;

    float acc[8][8];
    #pragma unroll
    for (int i = 0; i < 8; i++)
        #pragma unroll
        for (int j = 0; j < 8; j++) acc[i][j] = 0.0f;

    for (int k0 = 0; k0 < K; k0 += 8) {
        float4 av = make_float4(0.f, 0.f, 0.f, 0.f);
        int gr = row0 + arow;
        if (gr < M)
            av = *(const float4*)(A + (size_t)gr * K + k0 + acol);
        if (RELU_A) {
            av.x = fmaxf(av.x, 0.f); av.y = fmaxf(av.y, 0.f);
            av.z = fmaxf(av.z, 0.f); av.w = fmaxf(av.w, 0.f);
        }
        As[acol + 0][arow] = av.x;
        As[acol + 1][arow] = av.y;
        As[acol + 2][arow] = av.z;
        As[acol + 3][arow] = av.w;
        float4 bv = *(const float4*)(B + (size_t)(k0 + brow) * N + col0 + bcol);
        *(float4*)&Bs[brow][bcol] = bv;
        __syncthreads();

        #pragma unroll
        for (int k = 0; k < 8; k++) {
            float a[8], b[8];
            *(float4*)&a[0] = *(const float4*)&As[k][tm];
            *(float4*)&a[4] = *(const float4*)&As[k][tm + 4];
            *(float4*)&b[0] = *(const float4*)&Bs[k][tn];
            *(float4*)&b[4] = *(const float4*)&Bs[k][tn + 4];
            #pragma unroll
            for (int i = 0; i < 8; i++)
                #pragma unroll
                for (int j = 0; j < 8; j++)
                    acc[i][j] = fmaf(a[i], b[j], acc[i][j]);
        }
        __syncthreads();
    }

    #pragma unroll
    for (int i = 0; i < 8; i++) {
        int gr = row0 + tm + i;
        if (gr >= M) break;
        #pragma unroll
        for (int j = 0; j < 8; j += 4) {
            int gc = col0 + tn + j;
            float4 v;
            v.x = acc[i][j + 0] + bias[gc + 0];
            v.y = acc[i][j + 1] + bias[gc + 1];
            v.z = acc[i][j + 2] + bias[gc + 2];
            v.w = acc[i][j + 3] + bias[gc + 3];
            if (RELU_OUT) {
                v.x = fmaxf(v.x, 0.f); v.y = fmaxf(v.y, 0.f);
                v.z = fmaxf(v.z, 0.f); v.w = fmaxf(v.w, 0.f);
            }
            if (RES) {
                float4 r = *(const float4*)(res + (size_t)gr * N + gc);
                v.x += r.x; v.y += r.y; v.z += r.z; v.w += r.w;
            }
            *(float4*)(C + (size_t)gr * N + gc) = v;
        }
    }
}

// ---------------- edge pass 1: att = exp(q.k/sqrt(dk)), denom += att -------
__global__ void edge_att_kernel(const int* __restrict__ ei,
                                const float* __restrict__ Q,
                                const float* __restrict__ K)
{
    int t = blockIdx.x * blockDim.x + threadIdx.x;
    if (t >= N_EDGES * HEADS) return;
    int e = t >> 3;
    int h = t & 7;
    int r = ei[e];
    int s = ei[N_EDGES + e];
    const float4* q = (const float4*)(Q + (size_t)r * HD + h * DK);
    const float4* k = (const float4*)(K + (size_t)s * HD + h * DK);
    float dot = 0.0f;
    #pragma unroll
    for (int i = 0; i < 8; i++) {
        float4 a = q[i], b = k[i];
        dot += a.x * b.x + a.y * b.y + a.z * b.z + a.w * b.w;
    }
    float att = __expf(dot * 0.17677669529663688f);  // 1/sqrt(32)
    g_att[t] = att;
    atomicAdd(&g_denom[(size_t)r * HEADS + h], att);
}

// ---------------- edge pass 2: agg[recv] += (att/denom) * V[send] ----------
__global__ void edge_scatter_kernel(const int* __restrict__ ei,
                                    const float* __restrict__ V)
{
    int t = blockIdx.x * blockDim.x + threadIdx.x;
    if (t >= N_EDGES * 64) return;            // 64 float4 chunks per edge
    int e  = t >> 6;
    int c4 = t & 63;                          // chunk of 4 floats in [0,256)
    int h  = c4 >> 3;
    int r = ei[e];
    int s = ei[N_EDGES + e];
    float w = g_att[e * HEADS + h] / g_denom[(size_t)r * HEADS + h];
    float4 v = *(const float4*)(V + (size_t)s * HD + c4 * 4);
    float* dst = g_agg + (size_t)r * HD + c4 * 4;
    atomicAdd(dst + 0, w * v.x);
    atomicAdd(dst + 1, w * v.y);
    atomicAdd(dst + 2, w * v.z);
    atomicAdd(dst + 3, w * v.w);
}

// ---------------- launch ----------------------------------------------------
extern "C" void kernel_launch(void* const* d_in, const int* in_sizes, int n_in,
                              void* d_out, int out_size)
{
    const float* x  = (const float*)d_in[0];
    const int*   ei = (const int*)d_in[1];
    const float* Wk = (const float*)d_in[2];
    const float* bk = (const float*)d_in[3];
    const float* Wq = (const float*)d_in[4];
    const float* bq = (const float*)d_in[5];
    const float* Wv = (const float*)d_in[6];
    const float* bv = (const float*)d_in[7];
    const float* Wa = (const float*)d_in[8];
    const float* ba = (const float*)d_in[9];
    const float* Wf = (const float*)d_in[10];
    const float* bf = (const float*)d_in[11];
    float* out = (float*)d_out;

    float *gK, *gQ, *gV, *gAgg, *gH1;
    cudaGetSymbolAddress((void**)&gK,   g_K);
    cudaGetSymbolAddress((void**)&gQ,   g_Q);
    cudaGetSymbolAddress((void**)&gV,   g_V);
    cudaGetSymbolAddress((void**)&gAgg, g_agg);
    cudaGetSymbolAddress((void**)&gH1,  g_h1);

    const int MT = (N_NODES + 127) / 128;   // 391 row tiles

    zero_scratch<<<1024, 256>>>();

    // K, Q, V projections: [50000,512] @ [512,256]
    dim3 gProj(HD / 128, MT);
    sgemm128<false, false, false><<<gProj, 256>>>(x, Wk, bk, nullptr, gK,
                                                  N_NODES, HD, D_EMB);
    sgemm128<false, false, false><<<gProj, 256>>>(x, Wq, bq, nullptr, gQ,
                                                  N_NODES, HD, D_EMB);
    sgemm128<false, false, false><<<gProj, 256>>>(x, Wv, bv, nullptr, gV,
                                                  N_NODES, HD, D_EMB);

    // edge attention
    int nEH = N_EDGES * HEADS;
    edge_att_kernel<<<(nEH + 255) / 256, 256>>>(ei, gQ, gK);
    int nScatter = N_EDGES * 64;
    edge_scatter_kernel<<<(nScatter + 255) / 256, 256>>>(ei, gV);

    // out-proj: relu(agg) @ Wa + ba, relu   -> g_h1  [50000,256]@[256,512]
    dim3 gA(D_EMB / 128, MT);
    sgemm128<true, true, false><<<gA, 256>>>(gAgg, Wa, ba, nullptr, gH1,
                                             N_NODES, D_EMB, HD);

    // ffn: relu(h1 @ Wf + bf) + x -> out   [50000,512]@[512,512]
    dim3 gF(D_EMB / 128, MT);
    sgemm128<false, true, true><<<gF, 256>>>(gH1, Wf, bf, x, out,
                                             N_NODES, D_EMB, D_EMB);
}